// round 1
// baseline (speedup 1.0000x reference)
#include <cuda_runtime.h>

// Problem constants: shape (B=2, C=1, D=160, H=192, W=224), win=5, eps=1e-8
#define DD 160
#define HH 192
#define WW 224
#define BB 2
#define TX 32
#define TY 8
#define CHUNK 40          // z-outputs per block; 160/40 = 4 chunks
#define GX (WW / TX)      // 7
#define GY (HH / TY)      // 24
#define GZ (BB * (DD / CHUNK))  // 8
#define NBLOCKS (GX * GY * GZ)  // 1344
#define NTOT ((double)(BB) * DD * HH * WW)

__device__ double g_partials[NBLOCKS];

__global__ __launch_bounds__(256)
void ncc_main(const float* __restrict__ gI,
              const float* __restrict__ gJ,
              const float* __restrict__ gW)
{
    // raw slice tile with halo: (TY+4) rows x (TX+4) cols
    __shared__ float sI[TY + 4][TX + 4];
    __shared__ float sJ[TY + 4][TX + 4];
    // x-direction 5-window sums of the 5 quantities: [q][yy][x]
    __shared__ float xs[5][TY + 4][TX];
    __shared__ double sred[256];

    const int tid = threadIdx.x;
    const int x0 = blockIdx.x * TX;
    const int y0 = blockIdx.y * TY;
    const int cz = blockIdx.z & 3;       // chunk index (DD/CHUNK == 4)
    const int b  = blockIdx.z >> 2;      // batch
    const int z0 = cz * CHUNK;

    const int lx = tid & 31;             // 0..31 output x within tile
    const int ly = tid >> 5;             // 0..7  output y within tile

    const size_t base = (size_t)b * DD * HH * WW;

    // z ring buffer: 5 quantities x 5 slices, oldest at [*][0]
    float ring[5][5];
#pragma unroll
    for (int q = 0; q < 5; ++q)
#pragma unroll
        for (int s = 0; s < 5; ++s)
            ring[q][s] = 0.0f;

    float acc = 0.0f;

    for (int it = 0; it < CHUNK + 4; ++it) {
        const int zl = z0 - 2 + it;                 // slice being loaded
        const bool zin = (zl >= 0) && (zl < DD);

        // ---- load raw I,J slice tile (zero-padded OOB) ----
        for (int i = tid; i < (TY + 4) * (TX + 4); i += 256) {
            const int yy = i / (TX + 4);
            const int xx = i - yy * (TX + 4);
            const int gy = y0 + yy - 2;
            const int gx = x0 + xx - 2;
            float vi = 0.0f, vj = 0.0f;
            if (zin && (unsigned)gy < (unsigned)HH && (unsigned)gx < (unsigned)WW) {
                const size_t g = base + ((size_t)zl * HH + gy) * WW + gx;
                vi = gI[g];
                vj = gJ[g];
            }
            sI[yy][xx] = vi;
            sJ[yy][xx] = vj;
        }
        __syncthreads();

        // ---- x-direction 5-window sums of (I, J, I^2, J^2, I*J) ----
        for (int e = tid; e < (TY + 4) * TX; e += 256) {
            const int yy = e >> 5;       // TX == 32
            const int x  = e & 31;
            float a0 = 0.f, a1 = 0.f, a2 = 0.f, a3 = 0.f, a4 = 0.f;
#pragma unroll
            for (int dx = 0; dx < 5; ++dx) {
                const float vi = sI[yy][x + dx];
                const float vj = sJ[yy][x + dx];
                a0 += vi;
                a1 += vj;
                a2 = fmaf(vi, vi, a2);
                a3 = fmaf(vj, vj, a3);
                a4 = fmaf(vi, vj, a4);
            }
            xs[0][yy][x] = a0;
            xs[1][yy][x] = a1;
            xs[2][yy][x] = a2;
            xs[3][yy][x] = a3;
            xs[4][yy][x] = a4;
        }
        __syncthreads();

        // ---- y-direction 5-window sums -> per-slice values for this thread's column ----
        float q[5];
#pragma unroll
        for (int qq = 0; qq < 5; ++qq) {
            float s = 0.0f;
#pragma unroll
            for (int dy = 0; dy < 5; ++dy)
                s += xs[qq][ly + dy][lx];
            q[qq] = s;
        }

        // ---- shift z ring ----
#pragma unroll
        for (int qq = 0; qq < 5; ++qq) {
            ring[qq][0] = ring[qq][1];
            ring[qq][1] = ring[qq][2];
            ring[qq][2] = ring[qq][3];
            ring[qq][3] = ring[qq][4];
            ring[qq][4] = q[qq];
        }

        // ---- emit output for zo = zl - 2 once ring is primed ----
        if (it >= 4) {
            const int zo = zl - 2;       // in [z0, z0+CHUNK-1], always valid
            float SI = 0.f, SJ = 0.f, SII = 0.f, SJJ = 0.f, SIJ = 0.f;
#pragma unroll
            for (int s = 0; s < 5; ++s) {
                SI  += ring[0][s];
                SJ  += ring[1][s];
                SII += ring[2][s];
                SJJ += ring[3][s];
                SIJ += ring[4][s];
            }
            const float wsz = 125.0f;
            const float inv = 1.0f / 125.0f;
            const float uI = SI * inv;
            const float uJ = SJ * inv;
            const float cross = SIJ - uJ * SI - uI * SJ + uI * uJ * wsz;
            const float Ivar  = SII - 2.0f * uI * SI + uI * uI * wsz;
            const float Jvar  = SJJ - 2.0f * uJ * SJ + uJ * uJ * wsz;
            const float cc = (cross * cross) / (Ivar * Jvar + 1e-8f);
            const size_t g = base + ((size_t)zo * HH + (y0 + ly)) * WW + (x0 + lx);
            acc = fmaf(cc, gW[g], acc);
        }
    }

    // ---- block reduction (double), deterministic per-block partial ----
    sred[tid] = (double)acc;
    __syncthreads();
    for (int s = 128; s > 0; s >>= 1) {
        if (tid < s) sred[tid] += sred[tid + s];
        __syncthreads();
    }
    if (tid == 0) {
        const int bidx = ((int)blockIdx.z * GY + (int)blockIdx.y) * GX + (int)blockIdx.x;
        g_partials[bidx] = sred[0];
    }
}

__global__ __launch_bounds__(256)
void ncc_finalize(float* __restrict__ out)
{
    __shared__ double sred[256];
    double s = 0.0;
    for (int i = threadIdx.x; i < NBLOCKS; i += 256)
        s += g_partials[i];
    sred[threadIdx.x] = s;
    __syncthreads();
    for (int k = 128; k > 0; k >>= 1) {
        if (threadIdx.x < k) sred[threadIdx.x] += sred[threadIdx.x + k];
        __syncthreads();
    }
    if (threadIdx.x == 0)
        out[0] = (float)(-sred[0] / NTOT);
}

extern "C" void kernel_launch(void* const* d_in, const int* in_sizes, int n_in,
                              void* d_out, int out_size)
{
    const float* I = (const float*)d_in[0];
    const float* J = (const float*)d_in[1];
    const float* Wt = (const float*)d_in[2];
    float* out = (float*)d_out;

    dim3 grid(GX, GY, GZ);
    ncc_main<<<grid, 256>>>(I, J, Wt);
    ncc_finalize<<<1, 256>>>(out);
}